// round 6
// baseline (speedup 1.0000x reference)
#include <cuda_runtime.h>
#include <cuda_bf16.h>

#define N_NODES 100000
#define E_EDGES 1600000
#define FEAT 64
#define IN_DIM 128
#define OUT_DIM 64
#define HEADS 4
#define HID 16
#define EPS_C 0.5f

// Scratch (allocation-free: __device__ globals). 16B-aligned for float4 access.
__device__ __align__(16) float g_x[N_NODES * FEAT];     // relu(h @ t1_W + b)
__device__ __align__(16) float g_h0[N_NODES * FEAT];    // scatter accumulator
__device__ __align__(16) float g_pd[N_NODES * HEADS];   // dst-side gate projection
__device__ __align__(16) float g_ps[N_NODES * HEADS];   // src-side gate projection
__device__ float g_norm[N_NODES];
__device__ float g_deg[N_NODES];

// ---------------------------------------------------------------- zero
__global__ void zero_kernel() {
    int i = blockIdx.x * blockDim.x + threadIdx.x;
    if (i < N_NODES * FEAT) g_h0[i] = 0.0f;
    if (i < N_NODES) g_deg[i] = 0.0f;
}

// ---------------------------------------------------------------- degree
__global__ void deg_kernel(const int* __restrict__ dst) {
    int e = blockIdx.x * blockDim.x + threadIdx.x;
    if (e >= E_EDGES) return;
    atomicAdd(&g_deg[dst[e]], 1.0f);
}

// ---------------------------------------------------------------- norm
__global__ void norm_kernel() {
    int n = blockIdx.x * blockDim.x + threadIdx.x;
    if (n >= N_NODES) return;
    g_norm[n] = rsqrtf(fmaxf(g_deg[n], 1.0f));
}

// ---------------------------------------------------------------- GEMM1: x = relu(h @ W1 + b1)
// 8 rows per block, warp per row, 2 cols per lane. W1 (128x64) in smem.
__global__ __launch_bounds__(256) void gemm1_kernel(
    const float* __restrict__ h, const float* __restrict__ W,
    const float* __restrict__ b)
{
    __shared__ float ws[IN_DIM * FEAT];   // 32 KB
    __shared__ float hs[8 * IN_DIM];      // 4 KB
    int tid = threadIdx.x;
    for (int i = tid; i < IN_DIM * FEAT / 4; i += 256)
        ((float4*)ws)[i] = ((const float4*)W)[i];
    long long rowBase = (long long)blockIdx.x * 8;
    for (int i = tid; i < 8 * IN_DIM / 4; i += 256)
        ((float4*)hs)[i] = ((const float4*)(h + rowBase * IN_DIM))[i];
    __syncthreads();

    int w = tid >> 5, lane = tid & 31;
    long long row = rowBase + w;
    float2 acc = make_float2(0.f, 0.f);
    const float* hrow = hs + w * IN_DIM;
#pragma unroll 8
    for (int k = 0; k < IN_DIM; k++) {
        float hv = hrow[k];
        float2 wv = *(const float2*)(ws + k * FEAT + lane * 2);
        acc.x = fmaf(hv, wv.x, acc.x);
        acc.y = fmaf(hv, wv.y, acc.y);
    }
    float2 bias = *(const float2*)(b + lane * 2);
    acc.x = fmaxf(acc.x + bias.x, 0.f);
    acc.y = fmaxf(acc.y + bias.y, 0.f);
    *(float2*)(g_x + row * FEAT + lane * 2) = acc;
}

// ---------------------------------------------------------------- gate projections
// One thread per (node, head): pd = xh . w_d, ps = xh . w_s  (layer 1 weights only)
__global__ void pdps_kernel(const float* __restrict__ gate_W) {
    int t = blockIdx.x * blockDim.x + threadIdx.x;
    if (t >= N_NODES * HEADS) return;
    int n = t >> 2, hh = t & 3;
    const float* xr = g_x + (long long)n * FEAT + hh * HID;
    const float* wd = gate_W + 32;       // layer 1, dims [0:16)
    const float* wsrc = gate_W + 48;     // layer 1, dims [16:32)
    float a = 0.f, c = 0.f;
#pragma unroll
    for (int i = 0; i < HID; i++) {
        float xv = xr[i];
        a = fmaf(xv, __ldg(wd + i), a);
        c = fmaf(xv, __ldg(wsrc + i), c);
    }
    g_pd[t] = a;
    g_ps[t] = c;
}

// ---------------------------------------------------------------- edge kernel
// 16 threads per edge; each thread handles 4 contiguous features (one head per
// 4-thread group). Gather x[src] as float4, scatter via 4x scalar REDG.ADD.F32
// (vector float atomics are Hopper-only; they trap on sm_103a).
__global__ __launch_bounds__(256) void edge_kernel(
    const int* __restrict__ src, const int* __restrict__ dst,
    const float* __restrict__ gate_b)
{
    int t = blockIdx.x * blockDim.x + threadIdx.x;
    int e = t >> 4;
    if (e >= E_EDGES) return;
    int lane = t & 15;
    int head = lane >> 2;

    int s = __ldg(src + e);
    int d = __ldg(dst + e);

    float en = g_norm[d] * g_norm[s];
    float gb = __ldg(gate_b + 1);        // layer 1 bias
    float gate = tanhf(g_pd[d * 4 + head] + g_ps[s * 4 + head] + gb) * en;

    float4 v = *(const float4*)(g_x + (long long)s * FEAT + lane * 4);

    float* h0p = g_h0 + (long long)d * FEAT + lane * 4;
    atomicAdd(h0p + 0, v.x * gate);
    atomicAdd(h0p + 1, v.y * gate);
    atomicAdd(h0p + 2, v.z * gate);
    atomicAdd(h0p + 3, v.w * gate);
}

// ---------------------------------------------------------------- GEMM2: out = (EPS*x + h0) @ W2 + b2
__global__ __launch_bounds__(256) void gemm2_kernel(
    const float* __restrict__ W, const float* __restrict__ b,
    float* __restrict__ out)
{
    __shared__ float ws[FEAT * OUT_DIM];  // 16 KB
    __shared__ float as[8 * FEAT];        // 2 KB
    int tid = threadIdx.x;
    for (int i = tid; i < FEAT * OUT_DIM / 4; i += 256)
        ((float4*)ws)[i] = ((const float4*)W)[i];
    long long rowBase = (long long)blockIdx.x * 8;
    for (int i = tid; i < 8 * FEAT; i += 256) {
        long long gi = rowBase * FEAT + i;
        as[i] = EPS_C * g_x[gi] + g_h0[gi];
    }
    __syncthreads();

    int w = tid >> 5, lane = tid & 31;
    long long row = rowBase + w;
    float2 acc = make_float2(0.f, 0.f);
    const float* arow = as + w * FEAT;
#pragma unroll 8
    for (int k = 0; k < FEAT; k++) {
        float av = arow[k];
        float2 wv = *(const float2*)(ws + k * OUT_DIM + lane * 2);
        acc.x = fmaf(av, wv.x, acc.x);
        acc.y = fmaf(av, wv.y, acc.y);
    }
    float2 bias = *(const float2*)(b + lane * 2);
    acc.x += bias.x;
    acc.y += bias.y;
    *(float2*)(out + row * OUT_DIM + lane * 2) = acc;
}

// ---------------------------------------------------------------- launch
extern "C" void kernel_launch(void* const* d_in, const int* in_sizes, int n_in,
                              void* d_out, int out_size) {
    const float* h      = (const float*)d_in[0];
    const int*   src    = (const int*)d_in[1];   // JAX x64 disabled -> int32
    const int*   dst    = (const int*)d_in[2];   // JAX x64 disabled -> int32
    const float* t1_W   = (const float*)d_in[3];
    const float* t1_b   = (const float*)d_in[4];
    const float* t2_W   = (const float*)d_in[5];
    const float* t2_b   = (const float*)d_in[6];
    const float* gate_W = (const float*)d_in[7];
    const float* gate_b = (const float*)d_in[8];
    float* out = (float*)d_out;

    // 1. zero accumulators
    zero_kernel<<<(N_NODES * FEAT + 255) / 256, 256>>>();
    // 2. in-degrees
    deg_kernel<<<(E_EDGES + 255) / 256, 256>>>(dst);
    // 3. norm
    norm_kernel<<<(N_NODES + 255) / 256, 256>>>();
    // 4. x = relu(h @ W1 + b1)   (N divisible by 8 -> exact grid)
    gemm1_kernel<<<N_NODES / 8, 256>>>(h, t1_W, t1_b);
    // 5. gate projections (layer 1 only; layer 0 is dead in the reference)
    pdps_kernel<<<(N_NODES * HEADS + 255) / 256, 256>>>(gate_W);
    // 6. gather/gate/scatter over edges
    edge_kernel<<<(E_EDGES * 16) / 256, 256>>>(src, dst, gate_b);
    // 7. out = (EPS*x + h0) @ W2 + b2
    gemm2_kernel<<<N_NODES / 8, 256>>>(t2_W, t2_b, out);
}

// round 16
// speedup vs baseline: 1.4282x; 1.4282x over previous
#include <cuda_runtime.h>
#include <cuda_bf16.h>

#define N_NODES 100000
#define E_EDGES 1600000
#define FEAT 64
#define IN_DIM 128
#define OUT_DIM 64
#define HEADS 4
#define HID 16
#define EPS_C 0.5f
#define SCAN_BLOCKS 98   // ceil(100000/1024)

// ---------------- scratch (__device__ globals, no allocs) ----------------
__device__ __align__(16) float g_x[N_NODES * FEAT];      // relu(h@W1+b1)
__device__ __align__(16) float g_h1[N_NODES * FEAT];     // EPS*x + h0
__device__ __align__(16) float g_pd[N_NODES * HEADS];
__device__ __align__(16) float g_ps[N_NODES * HEADS];
__device__ float g_norm[N_NODES];
__device__ int   g_degi[N_NODES];
__device__ int   g_off[N_NODES + 1];
__device__ int   g_cursor[N_NODES];
__device__ int   g_partial[128];
__device__ int   g_esrc[E_EDGES];
__device__ __align__(16) float g_egate[E_EDGES * HEADS]; // per-edge per-head gate (binned order)

// ---------------- zero degree ----------------
__global__ void zero_deg_kernel() {
    int i = blockIdx.x * blockDim.x + threadIdx.x;
    if (i < N_NODES) g_degi[i] = 0;
}

// ---------------- in-degree histogram ----------------
__global__ void deg_kernel(const int* __restrict__ dst) {
    int e = blockIdx.x * blockDim.x + threadIdx.x;
    if (e < E_EDGES) atomicAdd(&g_degi[dst[e]], 1);
}

// ---------------- scan pass 1: per-block sums ----------------
__global__ __launch_bounds__(1024) void scan1_kernel() {
    __shared__ int red[32];
    int tid = threadIdx.x, lane = tid & 31, wid = tid >> 5;
    int i = blockIdx.x * 1024 + tid;
    int v = (i < N_NODES) ? g_degi[i] : 0;
    #pragma unroll
    for (int o = 16; o > 0; o >>= 1) v += __shfl_down_sync(0xffffffffu, v, o);
    if (lane == 0) red[wid] = v;
    __syncthreads();
    if (wid == 0) {
        int s = red[lane];
        #pragma unroll
        for (int o = 16; o > 0; o >>= 1) s += __shfl_down_sync(0xffffffffu, s, o);
        if (lane == 0) g_partial[blockIdx.x] = s;
    }
}

// ---------------- scan pass 2: exclusive scan of block sums (1 block) ----------------
__global__ __launch_bounds__(128) void scan2_kernel() {
    int tid = threadIdx.x, lane = tid & 31, wid = tid >> 5;
    int v = (tid < SCAN_BLOCKS) ? g_partial[tid] : 0;
    int inc = v;
    #pragma unroll
    for (int o = 1; o < 32; o <<= 1) {
        int t = __shfl_up_sync(0xffffffffu, inc, o);
        if (lane >= o) inc += t;
    }
    __shared__ int wsum[4];
    if (lane == 31) wsum[wid] = inc;
    __syncthreads();
    int add = 0;
    for (int j = 0; j < wid; j++) add += wsum[j];
    if (tid < SCAN_BLOCKS) g_partial[tid] = add + inc - v;   // exclusive
}

// ---------------- scan pass 3: offsets + cursors + norm ----------------
__global__ __launch_bounds__(1024) void scan3_kernel() {
    __shared__ int wsum[32];
    int tid = threadIdx.x, lane = tid & 31, wid = tid >> 5;
    int i = blockIdx.x * 1024 + tid;
    int d = (i < N_NODES) ? g_degi[i] : 0;
    int inc = d;
    #pragma unroll
    for (int o = 1; o < 32; o <<= 1) {
        int t = __shfl_up_sync(0xffffffffu, inc, o);
        if (lane >= o) inc += t;
    }
    if (lane == 31) wsum[wid] = inc;
    __syncthreads();
    if (wid == 0) {
        int s = wsum[lane];
        #pragma unroll
        for (int o = 1; o < 32; o <<= 1) {
            int t = __shfl_up_sync(0xffffffffu, s, o);
            if (lane >= o) s += t;
        }
        wsum[lane] = s;   // inclusive scan of warp sums
    }
    __syncthreads();
    int warpAdd = (wid > 0) ? wsum[wid - 1] : 0;
    int off = g_partial[blockIdx.x] + warpAdd + inc - d;     // exclusive
    if (i < N_NODES) {
        g_off[i] = off;
        g_cursor[i] = off;
        g_norm[i] = rsqrtf(fmaxf((float)d, 1.0f));
        if (i == N_NODES - 1) g_off[N_NODES] = off + d;
    }
}

// ---------------- GEMM1 (VERBATIM from the R6 kernel that PASSED on HW) ----------------
__global__ __launch_bounds__(256) void gemm1_kernel(
    const float* __restrict__ h, const float* __restrict__ W,
    const float* __restrict__ b)
{
    __shared__ float ws[IN_DIM * FEAT];   // 32 KB
    __shared__ float hs[8 * IN_DIM];      // 4 KB
    int tid = threadIdx.x;
    for (int i = tid; i < IN_DIM * FEAT / 4; i += 256)
        ((float4*)ws)[i] = ((const float4*)W)[i];
    long long rowBase = (long long)blockIdx.x * 8;
    for (int i = tid; i < 8 * IN_DIM / 4; i += 256)
        ((float4*)hs)[i] = ((const float4*)(h + rowBase * IN_DIM))[i];
    __syncthreads();

    int w = tid >> 5, lane = tid & 31;
    long long row = rowBase + w;
    float2 acc = make_float2(0.f, 0.f);
    const float* hrow = hs + w * IN_DIM;
#pragma unroll 8
    for (int k = 0; k < IN_DIM; k++) {
        float hv = hrow[k];
        float2 wv = *(const float2*)(ws + k * FEAT + lane * 2);
        acc.x = fmaf(hv, wv.x, acc.x);
        acc.y = fmaf(hv, wv.y, acc.y);
    }
    float2 bias = *(const float2*)(b + lane * 2);
    acc.x = fmaxf(acc.x + bias.x, 0.f);
    acc.y = fmaxf(acc.y + bias.y, 0.f);
    *(float2*)(g_x + row * FEAT + lane * 2) = acc;
}

// ---------------- gate projections (layer 1 only; layer 0 is dead) ----------------
__global__ void pdps_kernel(const float* __restrict__ gate_W) {
    int t = blockIdx.x * blockDim.x + threadIdx.x;
    if (t >= N_NODES * HEADS) return;
    int n = t >> 2, hh = t & 3;
    const float* xr = g_x + (long long)n * FEAT + hh * HID;
    const float* wd = gate_W + 32;       // layer 1, dims [0:16)
    const float* wsrc = gate_W + 48;     // layer 1, dims [16:32)
    float a = 0.f, c = 0.f;
    #pragma unroll
    for (int i = 0; i < HID; i++) {
        float xv = xr[i];
        a = fmaf(xv, __ldg(wd + i), a);
        c = fmaf(xv, __ldg(wsrc + i), c);
    }
    g_pd[t] = a;
    g_ps[t] = c;
}

// ---------------- binning: CSR scatter + per-edge gates (tanh once) ----------------
__global__ __launch_bounds__(256) void bin_kernel(
    const int* __restrict__ src, const int* __restrict__ dst,
    const float* __restrict__ gate_b)
{
    int e = blockIdx.x * blockDim.x + threadIdx.x;
    if (e >= E_EDGES) return;
    int s = __ldg(src + e);
    int d = __ldg(dst + e);
    float4 pdv = ((const float4*)g_pd)[d];
    float4 psv = ((const float4*)g_ps)[s];
    float en = g_norm[d] * g_norm[s];
    float gb = __ldg(gate_b + 1);        // layer 1 bias
    int p = atomicAdd(&g_cursor[d], 1);
    g_esrc[p] = s;
    float4 gt;
    gt.x = tanhf(pdv.x + psv.x + gb) * en;
    gt.y = tanhf(pdv.y + psv.y + gb) * en;
    gt.z = tanhf(pdv.z + psv.z + gb) * en;
    gt.w = tanhf(pdv.w + psv.w + gb) * en;
    ((float4*)g_egate)[p] = gt;
}

// ---------------- accumulate: one warp per dst node, no atomics ----------------
__global__ __launch_bounds__(256) void accum_kernel() {
    int node = (blockIdx.x << 3) + (threadIdx.x >> 5);   // grid exact: 12500*8 = N
    int lane = threadIdx.x & 31;
    int head = lane >> 3;                // feature f = lane*2 -> head = f/16 = lane/8
    int f0 = lane << 1;
    int start = g_off[node], end = g_off[node + 1];
    float2 acc = make_float2(0.f, 0.f);
    const float* ge = g_egate;
    for (int i = start; i < end; i++) {
        int s = __ldg(g_esrc + i);
        float gate = __ldg(ge + (size_t)i * 4 + head);
        float2 v = *(const float2*)(g_x + (size_t)s * FEAT + f0);
        acc.x = fmaf(v.x, gate, acc.x);
        acc.y = fmaf(v.y, gate, acc.y);
    }
    float2 xr = *(const float2*)(g_x + (size_t)node * FEAT + f0);
    acc.x = fmaf(EPS_C, xr.x, acc.x);
    acc.y = fmaf(EPS_C, xr.y, acc.y);
    *(float2*)(g_h1 + (size_t)node * FEAT + f0) = acc;
}

// ---------------- GEMM2 (R6 structure; reads pre-fused g_h1) ----------------
__global__ __launch_bounds__(256) void gemm2_kernel(
    const float* __restrict__ W, const float* __restrict__ b,
    float* __restrict__ out)
{
    __shared__ float ws[FEAT * OUT_DIM];  // 16 KB
    __shared__ float as[8 * FEAT];        // 2 KB
    int tid = threadIdx.x;
    for (int i = tid; i < FEAT * OUT_DIM / 4; i += 256)
        ((float4*)ws)[i] = ((const float4*)W)[i];
    long long rowBase = (long long)blockIdx.x * 8;
    for (int i = tid; i < 8 * FEAT; i += 256)
        as[i] = g_h1[rowBase * FEAT + i];
    __syncthreads();

    int w = tid >> 5, lane = tid & 31;
    long long row = rowBase + w;
    float2 acc = make_float2(0.f, 0.f);
    const float* arow = as + w * FEAT;
#pragma unroll 8
    for (int k = 0; k < FEAT; k++) {
        float av = arow[k];
        float2 wv = *(const float2*)(ws + k * OUT_DIM + lane * 2);
        acc.x = fmaf(av, wv.x, acc.x);
        acc.y = fmaf(av, wv.y, acc.y);
    }
    float2 bias = *(const float2*)(b + lane * 2);
    acc.x += bias.x;
    acc.y += bias.y;
    *(float2*)(out + row * OUT_DIM + lane * 2) = acc;
}

// ---------------- launch ----------------
extern "C" void kernel_launch(void* const* d_in, const int* in_sizes, int n_in,
                              void* d_out, int out_size) {
    const float* h      = (const float*)d_in[0];
    const int*   src    = (const int*)d_in[1];   // JAX x64 disabled -> int32
    const int*   dst    = (const int*)d_in[2];
    const float* t1_W   = (const float*)d_in[3];
    const float* t1_b   = (const float*)d_in[4];
    const float* t2_W   = (const float*)d_in[5];
    const float* t2_b   = (const float*)d_in[6];
    const float* gate_W = (const float*)d_in[7];
    const float* gate_b = (const float*)d_in[8];
    float* out = (float*)d_out;

    zero_deg_kernel<<<(N_NODES + 1023) / 1024, 1024>>>();
    deg_kernel<<<E_EDGES / 256, 256>>>(dst);
    scan1_kernel<<<SCAN_BLOCKS, 1024>>>();
    scan2_kernel<<<1, 128>>>();
    scan3_kernel<<<SCAN_BLOCKS, 1024>>>();
    gemm1_kernel<<<N_NODES / 8, 256>>>(h, t1_W, t1_b);           // proven R6 kernel
    pdps_kernel<<<(N_NODES * HEADS + 255) / 256, 256>>>(gate_W);
    bin_kernel<<<E_EDGES / 256, 256>>>(src, dst, gate_b);
    accum_kernel<<<N_NODES / 8, 256>>>();
    gemm2_kernel<<<N_NODES / 8, 256>>>(t2_W, t2_b, out);         // proven R6 structure
}

// round 17
// speedup vs baseline: 2.1234x; 1.4868x over previous
#include <cuda_runtime.h>
#include <cuda_bf16.h>

#define N_NODES 100000
#define E_EDGES 1600000
#define FEAT 64
#define IN_DIM 128
#define OUT_DIM 64
#define HEADS 4
#define HID 16
#define EPS_C 0.5f
#define SCAN_BLOCKS 98   // ceil(100000/1024)

// ---------------- scratch (__device__ globals, no allocs) ----------------
__device__ __align__(16) float g_x[N_NODES * FEAT];      // relu(h@W1+b1)
__device__ __align__(16) float g_h1[N_NODES * FEAT];     // EPS*x + h0
__device__ __align__(16) float g_pd[N_NODES * HEADS];
__device__ __align__(16) float g_ps[N_NODES * HEADS];
__device__ float g_norm[N_NODES];
__device__ int   g_degi[N_NODES];
__device__ int   g_off[N_NODES + 1];
__device__ int   g_cursor[N_NODES];
__device__ int   g_partial[128];
__device__ int   g_esrc[E_EDGES];
__device__ __align__(16) float g_egate[E_EDGES * HEADS]; // per-edge per-head gate (binned order)

// ---------------- zero degree ----------------
__global__ void zero_deg_kernel() {
    int i = blockIdx.x * blockDim.x + threadIdx.x;
    if (i < N_NODES) g_degi[i] = 0;
}

// ---------------- in-degree histogram ----------------
__global__ void deg_kernel(const int* __restrict__ dst) {
    int e = blockIdx.x * blockDim.x + threadIdx.x;
    if (e < E_EDGES) atomicAdd(&g_degi[dst[e]], 1);
}

// ---------------- scan pass 1: per-block sums ----------------
__global__ __launch_bounds__(1024) void scan1_kernel() {
    __shared__ int red[32];
    int tid = threadIdx.x, lane = tid & 31, wid = tid >> 5;
    int i = blockIdx.x * 1024 + tid;
    int v = (i < N_NODES) ? g_degi[i] : 0;
    #pragma unroll
    for (int o = 16; o > 0; o >>= 1) v += __shfl_down_sync(0xffffffffu, v, o);
    if (lane == 0) red[wid] = v;
    __syncthreads();
    if (wid == 0) {
        int s = red[lane];
        #pragma unroll
        for (int o = 16; o > 0; o >>= 1) s += __shfl_down_sync(0xffffffffu, s, o);
        if (lane == 0) g_partial[blockIdx.x] = s;
    }
}

// ---------------- scan pass 2: exclusive scan of block sums (1 block) ----------------
__global__ __launch_bounds__(128) void scan2_kernel() {
    int tid = threadIdx.x, lane = tid & 31, wid = tid >> 5;
    int v = (tid < SCAN_BLOCKS) ? g_partial[tid] : 0;
    int inc = v;
    #pragma unroll
    for (int o = 1; o < 32; o <<= 1) {
        int t = __shfl_up_sync(0xffffffffu, inc, o);
        if (lane >= o) inc += t;
    }
    __shared__ int wsum[4];
    if (lane == 31) wsum[wid] = inc;
    __syncthreads();
    int add = 0;
    for (int j = 0; j < wid; j++) add += wsum[j];
    if (tid < SCAN_BLOCKS) g_partial[tid] = add + inc - v;   // exclusive
}

// ---------------- scan pass 3: offsets + cursors + norm ----------------
__global__ __launch_bounds__(1024) void scan3_kernel() {
    __shared__ int wsum[32];
    int tid = threadIdx.x, lane = tid & 31, wid = tid >> 5;
    int i = blockIdx.x * 1024 + tid;
    int d = (i < N_NODES) ? g_degi[i] : 0;
    int inc = d;
    #pragma unroll
    for (int o = 1; o < 32; o <<= 1) {
        int t = __shfl_up_sync(0xffffffffu, inc, o);
        if (lane >= o) inc += t;
    }
    if (lane == 31) wsum[wid] = inc;
    __syncthreads();
    if (wid == 0) {
        int s = wsum[lane];
        #pragma unroll
        for (int o = 1; o < 32; o <<= 1) {
            int t = __shfl_up_sync(0xffffffffu, s, o);
            if (lane >= o) s += t;
        }
        wsum[lane] = s;   // inclusive scan of warp sums
    }
    __syncthreads();
    int warpAdd = (wid > 0) ? wsum[wid - 1] : 0;
    int off = g_partial[blockIdx.x] + warpAdd + inc - d;     // exclusive
    if (i < N_NODES) {
        g_off[i] = off;
        g_cursor[i] = off;
        g_norm[i] = rsqrtf(fmaxf((float)d, 1.0f));
        if (i == N_NODES - 1) g_off[N_NODES] = off + d;
    }
}

// ---------------- GEMM1: x = relu(h @ W1 + b1) ----------------
// Evolution of the PROVEN R6 kernel: same 256-thread shape, same smem staging,
// same lane->float2-column mapping. Delta: each warp now computes 4 rows
// (32 rows/block), with h read as float4 per 4-k chunk (warp-broadcast LDS).
// Crossbar per warp per 4k: 8 phases (W) + 4 phases (h) vs 16 cyc FMA -> FMA-bound.
__global__ __launch_bounds__(256) void gemm1_kernel(
    const float* __restrict__ h, const float* __restrict__ W,
    const float* __restrict__ b)
{
    __shared__ float ws[IN_DIM * FEAT];    // 32 KB
    __shared__ float hs[32 * IN_DIM];      // 16 KB  (total 48 KB static)
    int tid = threadIdx.x;
    for (int i = tid; i < IN_DIM * FEAT / 4; i += 256)
        ((float4*)ws)[i] = ((const float4*)W)[i];
    size_t rowBase = (size_t)blockIdx.x * 32;            // grid exact: 3125*32 = N
    for (int i = tid; i < 32 * IN_DIM / 4; i += 256)
        ((float4*)hs)[i] = ((const float4*)(h + rowBase * IN_DIM))[i];
    __syncthreads();

    int w = tid >> 5, lane = tid & 31;
    float2 acc[4];
    #pragma unroll
    for (int r = 0; r < 4; r++) acc[r] = make_float2(0.f, 0.f);

    for (int k0 = 0; k0 < IN_DIM; k0 += 4) {
        float4 hv[4];
        #pragma unroll
        for (int r = 0; r < 4; r++)
            hv[r] = *(const float4*)(hs + (w * 4 + r) * IN_DIM + k0);
        #pragma unroll
        for (int kk = 0; kk < 4; kk++) {
            float2 wv = *(const float2*)(ws + (k0 + kk) * FEAT + lane * 2);
            #pragma unroll
            for (int r = 0; r < 4; r++) {
                float hvk = ((const float*)&hv[r])[kk];
                acc[r].x = fmaf(hvk, wv.x, acc[r].x);
                acc[r].y = fmaf(hvk, wv.y, acc[r].y);
            }
        }
    }

    float2 bias = *(const float2*)(b + lane * 2);
    #pragma unroll
    for (int r = 0; r < 4; r++) {
        size_t row = rowBase + w * 4 + r;
        float lo = fmaxf(acc[r].x + bias.x, 0.f);
        float hi = fmaxf(acc[r].y + bias.y, 0.f);
        *(float2*)(g_x + row * FEAT + lane * 2) = make_float2(lo, hi);
    }
}

// ---------------- gate projections (layer 1 only; layer 0 is dead) ----------------
__global__ void pdps_kernel(const float* __restrict__ gate_W) {
    int t = blockIdx.x * blockDim.x + threadIdx.x;
    if (t >= N_NODES * HEADS) return;
    int n = t >> 2, hh = t & 3;
    const float* xr = g_x + (long long)n * FEAT + hh * HID;
    const float* wd = gate_W + 32;       // layer 1, dims [0:16)
    const float* wsrc = gate_W + 48;     // layer 1, dims [16:32)
    float a = 0.f, c = 0.f;
    #pragma unroll
    for (int i = 0; i < HID; i++) {
        float xv = xr[i];
        a = fmaf(xv, __ldg(wd + i), a);
        c = fmaf(xv, __ldg(wsrc + i), c);
    }
    g_pd[t] = a;
    g_ps[t] = c;
}

// ---------------- binning: CSR scatter + per-edge gates (tanh once) ----------------
__global__ __launch_bounds__(256) void bin_kernel(
    const int* __restrict__ src, const int* __restrict__ dst,
    const float* __restrict__ gate_b)
{
    int e = blockIdx.x * blockDim.x + threadIdx.x;
    if (e >= E_EDGES) return;
    int s = __ldg(src + e);
    int d = __ldg(dst + e);
    float4 pdv = ((const float4*)g_pd)[d];
    float4 psv = ((const float4*)g_ps)[s];
    float en = g_norm[d] * g_norm[s];
    float gb = __ldg(gate_b + 1);        // layer 1 bias
    int p = atomicAdd(&g_cursor[d], 1);
    g_esrc[p] = s;
    float4 gt;
    gt.x = tanhf(pdv.x + psv.x + gb) * en;
    gt.y = tanhf(pdv.y + psv.y + gb) * en;
    gt.z = tanhf(pdv.z + psv.z + gb) * en;
    gt.w = tanhf(pdv.w + psv.w + gb) * en;
    ((float4*)g_egate)[p] = gt;
}

// ---------------- accumulate: one warp per dst node, no atomics ----------------
__global__ __launch_bounds__(256) void accum_kernel() {
    int node = (blockIdx.x << 3) + (threadIdx.x >> 5);   // grid exact: 12500*8 = N
    int lane = threadIdx.x & 31;
    int head = lane >> 3;                // feature f = lane*2 -> head = f/16 = lane/8
    int f0 = lane << 1;
    int start = g_off[node], end = g_off[node + 1];
    float2 acc = make_float2(0.f, 0.f);
    const float* ge = g_egate;
    for (int i = start; i < end; i++) {
        int s = __ldg(g_esrc + i);
        float gate = __ldg(ge + (size_t)i * 4 + head);
        float2 v = *(const float2*)(g_x + (size_t)s * FEAT + f0);
        acc.x = fmaf(v.x, gate, acc.x);
        acc.y = fmaf(v.y, gate, acc.y);
    }
    float2 xr = *(const float2*)(g_x + (size_t)node * FEAT + f0);
    acc.x = fmaf(EPS_C, xr.x, acc.x);
    acc.y = fmaf(EPS_C, xr.y, acc.y);
    *(float2*)(g_h1 + (size_t)node * FEAT + f0) = acc;
}

// ---------------- GEMM2: out = h1 @ W2 + b2 (same restructure as gemm1) ----------------
__global__ __launch_bounds__(256) void gemm2_kernel(
    const float* __restrict__ W, const float* __restrict__ b,
    float* __restrict__ out)
{
    __shared__ float ws[FEAT * OUT_DIM];   // 16 KB
    __shared__ float hs[32 * FEAT];        // 8 KB
    int tid = threadIdx.x;
    for (int i = tid; i < FEAT * OUT_DIM / 4; i += 256)
        ((float4*)ws)[i] = ((const float4*)W)[i];
    size_t rowBase = (size_t)blockIdx.x * 32;            // grid exact
    for (int i = tid; i < 32 * FEAT / 4; i += 256)
        ((float4*)hs)[i] = ((const float4*)(g_h1 + rowBase * FEAT))[i];
    __syncthreads();

    int w = tid >> 5, lane = tid & 31;
    float2 acc[4];
    #pragma unroll
    for (int r = 0; r < 4; r++) acc[r] = make_float2(0.f, 0.f);

    for (int k0 = 0; k0 < FEAT; k0 += 4) {
        float4 hv[4];
        #pragma unroll
        for (int r = 0; r < 4; r++)
            hv[r] = *(const float4*)(hs + (w * 4 + r) * FEAT + k0);
        #pragma unroll
        for (int kk = 0; kk < 4; kk++) {
            float2 wv = *(const float2*)(ws + (k0 + kk) * OUT_DIM + lane * 2);
            #pragma unroll
            for (int r = 0; r < 4; r++) {
                float hvk = ((const float*)&hv[r])[kk];
                acc[r].x = fmaf(hvk, wv.x, acc[r].x);
                acc[r].y = fmaf(hvk, wv.y, acc[r].y);
            }
        }
    }

    float2 bias = *(const float2*)(b + lane * 2);
    #pragma unroll
    for (int r = 0; r < 4; r++) {
        size_t row = rowBase + w * 4 + r;
        *(float2*)(out + row * OUT_DIM + lane * 2) =
            make_float2(acc[r].x + bias.x, acc[r].y + bias.y);
    }
}

// ---------------- launch ----------------
extern "C" void kernel_launch(void* const* d_in, const int* in_sizes, int n_in,
                              void* d_out, int out_size) {
    const float* h      = (const float*)d_in[0];
    const int*   src    = (const int*)d_in[1];   // JAX x64 disabled -> int32
    const int*   dst    = (const int*)d_in[2];
    const float* t1_W   = (const float*)d_in[3];
    const float* t1_b   = (const float*)d_in[4];
    const float* t2_W   = (const float*)d_in[5];
    const float* t2_b   = (const float*)d_in[6];
    const float* gate_W = (const float*)d_in[7];
    const float* gate_b = (const float*)d_in[8];
    float* out = (float*)d_out;

    zero_deg_kernel<<<(N_NODES + 1023) / 1024, 1024>>>();
    deg_kernel<<<E_EDGES / 256, 256>>>(dst);
    scan1_kernel<<<SCAN_BLOCKS, 1024>>>();
    scan2_kernel<<<1, 128>>>();
    scan3_kernel<<<SCAN_BLOCKS, 1024>>>();
    gemm1_kernel<<<N_NODES / 32, 256>>>(h, t1_W, t1_b);   // 3125 blocks, exact
    pdps_kernel<<<(N_NODES * HEADS + 255) / 256, 256>>>(gate_W);
    bin_kernel<<<E_EDGES / 256, 256>>>(src, dst, gate_b);
    accum_kernel<<<N_NODES / 8, 256>>>();
    gemm2_kernel<<<N_NODES / 32, 256>>>(t2_W, t2_b, out); // 3125 blocks, exact
}